// round 14
// baseline (speedup 1.0000x reference)
#include <cuda_runtime.h>
#include <cuda_bf16.h>

#define NB 128
#define NU 16
#define NA 1024
#define NO 8
#define NT 16            // partial-slot granularity (64-antenna tiles)

typedef unsigned long long u64;

// ---- persistent scratch (no allocations allowed) ----
__device__ float g_fll[3][(size_t)NB * NA * NU * NO];
__device__ float g_sgl[3][(size_t)NB * NA * NO];
__device__ float g_plg[4][NB * NT * NU * NO];
__device__ float g_pgg[4][NB * NT * NO];

__device__ __forceinline__ u64 pack2(float x) {
    u64 r; asm("mov.b64 %0, {%1, %1};" : "=l"(r) : "f"(x)); return r;
}
__device__ __forceinline__ float2 unpack2(u64 v) {
    float2 r; asm("mov.b64 {%0, %1}, %2;" : "=f"(r.x), "=f"(r.y) : "l"(v)); return r;
}
__device__ __forceinline__ u64 repack(float x, float y) {
    u64 r; asm("mov.b64 %0, {%1, %2};" : "=l"(r) : "f"(x), "f"(y)); return r;
}
#define FMA2(d, a, b, c) asm("fma.rn.f32x2 %0, %1, %2, %3;" : "=l"(d) : "l"(a), "l"(b), "l"(c))
#define ADD2(d, a, b)    asm("add.rn.f32x2 %0, %1, %2;"     : "=l"(d) : "l"(a), "l"(b))

__device__ __forceinline__ u64 relu2(u64 x) {
    float2 p = unpack2(x);
    return repack(fmaxf(p.x, 0.0f), fmaxf(p.y, 0.0f));
}
__device__ __forceinline__ u64 shfl64(u64 v, int m) {
    return __shfl_xor_sync(0xffffffffu, v, m);
}

// =============================================================================
// Branch core: 4 points/thread at a = aBase + alq + STEP*i  (STEP = #alq lanes
// = threads/16). Packed FMA mainloop + packed shuffle-tree epilogues (R5).
// =============================================================================
template <int STEP, int CIN, int BSTR, bool ADDA>
__device__ __forceinline__ void branch_full(
    int b, int aBase, int tid, const float (*v)[CIN],
    const float* __restrict__ sW,
    const float* __restrict__ sAddU, const float* __restrict__ sAddA,
    float* __restrict__ fll_out, float* __restrict__ sgl_out,
    float* __restrict__ sRedLg, float* __restrict__ sRedGg)
{
    const int u = tid & 15, alq = tid >> 4, warp = tid >> 5, lane = tid & 31;

    #pragma unroll
    for (int br = 0; br < 4; br++) {
        const ulonglong2* aup = (const ulonglong2*)(sAddU + (br * 16 + u) * 8);
        const ulonglong2 au0 = aup[0], au1 = aup[1];
        u64 z2[4][4];
        #pragma unroll
        for (int i = 0; i < 4; i++) {
            if (ADDA) {
                const ulonglong2* ap = (const ulonglong2*)
                    (sAddA + (br * 4 * STEP + alq + STEP * i) * 8);
                ulonglong2 a0 = ap[0], a1 = ap[1];
                ADD2(z2[i][0], au0.x, a0.x);
                ADD2(z2[i][1], au0.y, a0.y);
                ADD2(z2[i][2], au1.x, a1.x);
                ADD2(z2[i][3], au1.y, a1.y);
            } else {
                z2[i][0] = au0.x; z2[i][1] = au0.y;
                z2[i][2] = au1.x; z2[i][3] = au1.y;
            }
        }
        #pragma unroll
        for (int c = 0; c < CIN; c++) {
            const ulonglong2* wp = (const ulonglong2*)(sW + (br * BSTR + c) * 8);
            const ulonglong2 w0 = wp[0], w1 = wp[1];
            #pragma unroll
            for (int i = 0; i < 4; i++) {
                u64 v2 = pack2(v[i][c]);
                FMA2(z2[i][0], v2, w0.x, z2[i][0]);
                FMA2(z2[i][1], v2, w0.y, z2[i][1]);
                FMA2(z2[i][2], v2, w1.x, z2[i][2]);
                FMA2(z2[i][3], v2, w1.y, z2[i][3]);
            }
        }
        #pragma unroll
        for (int i = 0; i < 4; i++)
            #pragma unroll
            for (int j = 0; j < 4; j++)
                z2[i][j] = relu2(z2[i][j]);

        if (br == 0) {                       // ll: packed pointwise store
            #pragma unroll
            for (int i = 0; i < 4; i++) {
                int a = aBase + alq + STEP * i;
                size_t idx = (((size_t)b * NA + a) * NU + u) * NO;
                ulonglong2 r0, r1;
                r0.x = z2[i][0]; r0.y = z2[i][1];
                r1.x = z2[i][2]; r1.y = z2[i][3];
                *(ulonglong2*)(fll_out + idx)     = r0;
                *(ulonglong2*)(fll_out + idx + 4) = r1;
            }
        } else if (br == 1) {                // lg: reg-accumulate, fold warp
            u64 acc[4];
            #pragma unroll
            for (int j = 0; j < 4; j++) {
                u64 t0, t1;
                ADD2(t0, z2[0][j], z2[1][j]);
                ADD2(t1, z2[2][j], z2[3][j]);
                ADD2(acc[j], t0, t1);
            }
            const bool hA = (lane & 16);
            u64 sa = hA ? acc[0] : acc[2];
            u64 sb = hA ? acc[1] : acc[3];
            u64 ka = hA ? acc[2] : acc[0];
            u64 kb = hA ? acc[3] : acc[1];
            u64 ra = shfl64(sa, 16), rb = shfl64(sb, 16);
            ADD2(ka, ka, ra); ADD2(kb, kb, rb);
            ulonglong2 st; st.x = ka; st.y = kb;
            *(ulonglong2*)(sRedLg + warp * 128 + u * 8 + (hA ? 4 : 0)) = st;
        } else if (br == 2) {                // gl: packed tree over 16 u-lanes
            const bool h8 = (u & 8), h4 = (u & 4), h2 = (u & 2);
            #pragma unroll
            for (int i = 0; i < 4; i++) {
                u64 sa = h8 ? z2[i][0] : z2[i][2];
                u64 sb = h8 ? z2[i][1] : z2[i][3];
                u64 ka = h8 ? z2[i][2] : z2[i][0];
                u64 kb = h8 ? z2[i][3] : z2[i][1];
                u64 ra = shfl64(sa, 8), rb = shfl64(sb, 8);
                ADD2(ka, ka, ra); ADD2(kb, kb, rb);
                u64 s1 = h4 ? ka : kb, k1 = h4 ? kb : ka;
                u64 r1 = shfl64(s1, 4);
                ADD2(k1, k1, r1);
                float2 p = unpack2(k1);
                float snd = h2 ? p.x : p.y;
                float t = (h2 ? p.y : p.x) + __shfl_xor_sync(0xffffffffu, snd, 2);
                t += __shfl_xor_sync(0xffffffffu, t, 1);
                if (!(u & 1)) {
                    int o = (h8 ? 4 : 0) + (h4 ? 2 : 0) + (h2 ? 1 : 0);
                    int a = aBase + alq + STEP * i;
                    sgl_out[((size_t)b * NA + a) * NO + o] = t;
                }
            }
        } else {                             // gg: packed tree over 32 lanes
            u64 acc[4];
            #pragma unroll
            for (int j = 0; j < 4; j++) {
                u64 t0, t1;
                ADD2(t0, z2[0][j], z2[1][j]);
                ADD2(t1, z2[2][j], z2[3][j]);
                ADD2(acc[j], t0, t1);
            }
            const bool b0 = (lane & 1), b1 = (lane & 2), b2 = (lane & 4);
            u64 sa = b0 ? acc[0] : acc[2];
            u64 sb = b0 ? acc[1] : acc[3];
            u64 ka = b0 ? acc[2] : acc[0];
            u64 kb = b0 ? acc[3] : acc[1];
            u64 ra = shfl64(sa, 1), rb = shfl64(sb, 1);
            ADD2(ka, ka, ra); ADD2(kb, kb, rb);
            u64 s1 = b1 ? ka : kb, k1 = b1 ? kb : ka;
            u64 r1 = shfl64(s1, 2);
            ADD2(k1, k1, r1);
            float2 p = unpack2(k1);
            float snd = b2 ? p.x : p.y;
            float t = (b2 ? p.y : p.x) + __shfl_xor_sync(0xffffffffu, snd, 4);
            t += __shfl_xor_sync(0xffffffffu, t, 8);
            t += __shfl_xor_sync(0xffffffffu, t, 16);
            if (lane < 8) {
                int o = (b0 ? 4 : 0) + (b1 ? 2 : 0) + (b2 ? 1 : 0);
                sRedGg[warp * 8 + o] = t;
            }
        }
    }
}

// NW = warps per CTA. Writes one partial slot (slot index in units of NT=16).
template <int NW>
__device__ __forceinline__ void write_partials(int b, int slot, int tid, int po,
    const float* __restrict__ sRedLg, const float* __restrict__ sRedGg)
{
    if (tid < 128) {
        float s = 0.0f;
        #pragma unroll
        for (int w = 0; w < NW; w++) s += sRedLg[w * 128 + tid];
        g_plg[po][(b * NT + slot) * 128 + tid] = s;
    }
    if (tid < 8) {
        float s = 0.0f;
        #pragma unroll
        for (int w = 0; w < NW; w++) s += sRedGg[w * 8 + tid];
        g_pgg[po][(b * NT + slot) * 8 + tid] = s;
    }
}

// =============================================================================
// Layer 1 (256 threads, 64-antenna tile): channel -> state 0, 16 partial slots
// =============================================================================
__global__ void __launch_bounds__(256)
k_layer1(const float* __restrict__ ch, const float* __restrict__ W1,
         const float* __restrict__ b1)
{
    __shared__ float sCh[4 * 16 * 65];
    __shared__ float sW[128], sAddU[512];
    __shared__ float sRedLg[1024], sRedGg[64];
    const int tile = blockIdx.x, b = blockIdx.y, tid = threadIdx.x;

    for (int e = tid; e < 4096; e += 256) {
        int c = e >> 10, uu = (e >> 6) & 15, al = e & 63;
        sCh[c * 1040 + uu * 65 + al] =
            ch[(((size_t)b * 4 + c) * NU + uu) * NA + (size_t)tile * 64 + al];
    }
    if (tid < 128) sW[tid] = W1[tid];
    #pragma unroll
    for (int k = 0; k < 2; k++) {
        int e = tid + 256 * k, br = e >> 7, o = e & 7;
        sAddU[e] = b1[br * 8 + o];
    }
    __syncthreads();

    const int u = tid & 15, alq = tid >> 4;
    float v[4][4];
    #pragma unroll
    for (int i = 0; i < 4; i++)
        #pragma unroll
        for (int c = 0; c < 4; c++)
            v[i][c] = sCh[c * 1040 + u * 65 + alq + 16 * i];

    branch_full<16, 4, 4, false>(b, tile * 64, tid, v, sW, sAddU, nullptr,
                                 g_fll[0], g_sgl[0], sRedLg, sRedGg);
    __syncthreads();
    write_partials<8>(b, tile, tid, 0, sRedLg, sRedGg);
}

// =============================================================================
// WIDE middle layer: 512 threads, 128-antenna tile, 1 CTA/SM.
// Per-128-antenna prologue (plg/pgg reduce over nti slots, addU, weights).
// Emits ONE partial slot per CTA (8 slots/b).
// =============================================================================
__global__ void __launch_bounds__(512)
k_mainw(const float* __restrict__ W, const float* __restrict__ bias,
        int si, int so, int pi, int po, int nti)
{
    __shared__ float sW[1024], sAddU[512], sAddA[4096];
    __shared__ float sSgl[1024], sFlg[128], sFgg[8];
    __shared__ float sRedLg[2048], sRedGg[128];
    const int tile = blockIdx.x, b = blockIdx.y, tid = threadIdx.x;
    const int u = tid & 15, alq = tid >> 4;     // alq in 0..31

    // ---- prefetch v (before any barrier) ----
    const float* __restrict__ fin = g_fll[si];
    float4 vp[4][2];
    #pragma unroll
    for (int i = 0; i < 4; i++) {
        int a = tile * 128 + alq + 32 * i;
        size_t idx = (((size_t)b * NA + a) * NU + u) * NO;
        vp[i][0] = *(const float4*)(fin + idx);
        vp[i][1] = *(const float4*)(fin + idx + 4);
    }

    // ---- prologue: weights + small components (once per 128 antennas) ----
    if (tid < 256) ((float4*)sW)[tid] = ((const float4*)W)[tid];
    if (tid < 256) {
        size_t base = ((size_t)b * NA + (size_t)tile * 128) * NO;
        ((float4*)sSgl)[tid] = ((const float4*)(g_sgl[si] + base))[tid];
    }
    if (tid < 128) {
        float s = 0.0f;
        for (int t = 0; t < nti; t++) s += g_plg[pi][(b * NT + t) * 128 + tid];
        sFlg[tid] = s * (1.0f / NA);
    }
    if (tid < 8) {
        float s = 0.0f;
        for (int t = 0; t < nti; t++) s += g_pgg[pi][(b * NT + t) * 8 + tid];
        sFgg[tid] = s * (1.0f / (NA * NU));
    }
    __syncthreads();

    // addU[br][u][o] — 512 entries, one per thread
    {
        int br = tid >> 7, uu = (tid >> 3) & 15, o = tid & 7;
        float acc = bias[br * 8 + o];
        #pragma unroll
        for (int c = 0; c < 8; c++) {
            acc += sFgg[c]          * sW[(br * 32 + 24 + c) * 8 + o];
            acc += sFlg[uu * 8 + c] * sW[(br * 32 +  8 + c) * 8 + o];
        }
        sAddU[tid] = acc;
    }
    // addA[br][al][o] — 4096 entries, 8 per thread
    #pragma unroll
    for (int k = 0; k < 8; k++) {
        int e = tid + 512 * k, br = e >> 10, al = (e >> 3) & 127, o = e & 7;
        float acc = 0.0f;
        #pragma unroll
        for (int c = 0; c < 8; c++)
            acc += sSgl[al * 8 + c] * sW[(br * 32 + 16 + c) * 8 + o];
        sAddA[e] = acc * (1.0f / 16.0f);
    }
    __syncthreads();

    float v[4][8];
    #pragma unroll
    for (int i = 0; i < 4; i++) {
        float4 p0 = vp[i][0], p1 = vp[i][1];
        v[i][0] = p0.x; v[i][1] = p0.y; v[i][2] = p0.z; v[i][3] = p0.w;
        v[i][4] = p1.x; v[i][5] = p1.y; v[i][6] = p1.z; v[i][7] = p1.w;
    }

    branch_full<32, 8, 32, true>(b, tile * 128, tid, v, sW, sAddU, sAddA,
                                 g_fll[so], g_sgl[so], sRedLg, sRedGg);
    __syncthreads();
    write_partials<16>(b, tile, tid, po, sRedLg, sRedGg);
}

// =============================================================================
// SKIP middle layer (256 threads, R5 path; two input states, mixed slot counts)
// =============================================================================
__global__ void __launch_bounds__(256)
k_main_skip(const float* __restrict__ W, const float* __restrict__ bias,
            int si, int si2, int so, int pi, int pi2, int po,
            int nti, int nti2)
{
    __shared__ float sW[1024], sAddU[512], sAddA[2048];
    __shared__ float sSgl[512], sFlg[128], sFgg[8];
    __shared__ float sRedLg[1024], sRedGg[64];
    const int tile = blockIdx.x, b = blockIdx.y, tid = threadIdx.x;
    const int u = tid & 15, alq = tid >> 4;

    const float* __restrict__ fin  = g_fll[si];
    const float* __restrict__ fin2 = g_fll[si2];
    float4 vp[4][2], vq[4][2];
    #pragma unroll
    for (int i = 0; i < 4; i++) {
        int a = tile * 64 + alq + 16 * i;
        size_t idx = (((size_t)b * NA + a) * NU + u) * NO;
        vp[i][0] = *(const float4*)(fin + idx);
        vp[i][1] = *(const float4*)(fin + idx + 4);
        vq[i][0] = *(const float4*)(fin2 + idx);
        vq[i][1] = *(const float4*)(fin2 + idx + 4);
    }

    ((float4*)sW)[tid] = ((const float4*)W)[tid];
    if (tid < 128) {
        size_t base = ((size_t)b * NA + (size_t)tile * 64) * NO;
        float4 p = ((const float4*)(g_sgl[si] + base))[tid];
        float4 q = ((const float4*)(g_sgl[si2] + base))[tid];
        p.x = 0.5f * (p.x + q.x); p.y = 0.5f * (p.y + q.y);
        p.z = 0.5f * (p.z + q.z); p.w = 0.5f * (p.w + q.w);
        ((float4*)sSgl)[tid] = p;

        float s = 0.0f, s2 = 0.0f;
        for (int t = 0; t < nti; t++)  s  += g_plg[pi][(b * NT + t) * 128 + tid];
        for (int t = 0; t < nti2; t++) s2 += g_plg[pi2][(b * NT + t) * 128 + tid];
        sFlg[tid] = 0.5f * (s + s2) * (1.0f / NA);
    }
    if (tid < 8) {
        float s = 0.0f, s2 = 0.0f;
        for (int t = 0; t < nti; t++)  s  += g_pgg[pi][(b * NT + t) * 8 + tid];
        for (int t = 0; t < nti2; t++) s2 += g_pgg[pi2][(b * NT + t) * 8 + tid];
        sFgg[tid] = 0.5f * (s + s2) * (1.0f / (NA * NU));
    }
    __syncthreads();

    #pragma unroll
    for (int k = 0; k < 2; k++) {
        int e = tid + 256 * k, br = e >> 7, uu = (e >> 3) & 15, o = e & 7;
        float acc = bias[br * 8 + o];
        #pragma unroll
        for (int c = 0; c < 8; c++) {
            acc += sFgg[c]          * sW[(br * 32 + 24 + c) * 8 + o];
            acc += sFlg[uu * 8 + c] * sW[(br * 32 +  8 + c) * 8 + o];
        }
        sAddU[e] = acc;
    }
    #pragma unroll
    for (int k = 0; k < 8; k++) {
        int e = tid + 256 * k, br = e >> 9, al = (e >> 3) & 63, o = e & 7;
        float acc = 0.0f;
        #pragma unroll
        for (int c = 0; c < 8; c++)
            acc += sSgl[al * 8 + c] * sW[(br * 32 + 16 + c) * 8 + o];
        sAddA[e] = acc * (1.0f / 16.0f);
    }
    __syncthreads();

    float v[4][8];
    #pragma unroll
    for (int i = 0; i < 4; i++) {
        float4 p0 = vp[i][0], p1 = vp[i][1];
        float4 q0 = vq[i][0], q1 = vq[i][1];
        p0.x = 0.5f * (p0.x + q0.x); p0.y = 0.5f * (p0.y + q0.y);
        p0.z = 0.5f * (p0.z + q0.z); p0.w = 0.5f * (p0.w + q0.w);
        p1.x = 0.5f * (p1.x + q1.x); p1.y = 0.5f * (p1.y + q1.y);
        p1.z = 0.5f * (p1.z + q1.z); p1.w = 0.5f * (p1.w + q1.w);
        v[i][0] = p0.x; v[i][1] = p0.y; v[i][2] = p0.z; v[i][3] = p0.w;
        v[i][4] = p1.x; v[i][5] = p1.y; v[i][6] = p1.z; v[i][7] = p1.w;
    }

    branch_full<16, 8, 32, true>(b, tile * 64, tid, v, sW, sAddU, sAddA,
                                 g_fll[so], g_sgl[so], sRedLg, sRedGg);
    __syncthreads();
    write_partials<8>(b, tile, tid, po, sRedLg, sRedGg);
}

// =============================================================================
// Final: out[b, a] = pi * mean_u( conv(f_avg, W8) + b8 )
// =============================================================================
__global__ void __launch_bounds__(256)
k_final(const float* __restrict__ W8, const float* __restrict__ b8,
        float* __restrict__ out, int s1, int s2, int p1, int p2, int ntp)
{
    __shared__ float sW8[32];
    __shared__ float sFlg[128], sFgg[8];
    __shared__ float cU[17];
    const int tile = blockIdx.x, b = blockIdx.y, tid = threadIdx.x;
    if (tid < 32) sW8[tid] = W8[tid];
    if (tid < 128) {
        float s = 0.0f;
        for (int t = 0; t < ntp; t++)
            s += g_plg[p1][(b * NT + t) * 128 + tid] +
                 g_plg[p2][(b * NT + t) * 128 + tid];
        sFlg[tid] = s * (0.5f / NA);
    }
    if (tid < 8) {
        float s = 0.0f;
        for (int t = 0; t < ntp; t++)
            s += g_pgg[p1][(b * NT + t) * 8 + tid] +
                 g_pgg[p2][(b * NT + t) * 8 + tid];
        sFgg[tid] = s * (0.5f / (NA * NU));
    }
    __syncthreads();
    if (tid < 16) {
        float s = 0.0f;
        #pragma unroll
        for (int c = 0; c < 8; c++)
            s += sFlg[tid * 8 + c] * sW8[8 + c];
        cU[tid] = s;
    }
    __syncthreads();
    if (tid == 0) {
        float s = 0.0f;
        for (int uu = 0; uu < 16; uu++) s += cU[uu];
        s *= (1.0f / 16.0f);
        #pragma unroll
        for (int c = 0; c < 8; c++) s += sFgg[c] * sW8[24 + c];
        s += b8[0];
        cU[16] = s;
    }
    __syncthreads();
    const float cb = cU[16];
    const int u = tid & 15, alq = tid >> 4;
    const float* __restrict__ f1 = g_fll[s1];
    const float* __restrict__ f2 = g_fll[s2];
    #pragma unroll
    for (int i = 0; i < 4; i++) {
        int a = tile * 64 + alq + 16 * i;
        size_t idx = (((size_t)b * NA + a) * NU + u) * NO;
        float4 p0 = *(const float4*)(f1 + idx);
        float4 p1 = *(const float4*)(f1 + idx + 4);
        float4 q0 = *(const float4*)(f2 + idx);
        float4 q1 = *(const float4*)(f2 + idx + 4);
        float d = 0.0f;
        d += 0.5f * (p0.x + q0.x) * sW8[0];
        d += 0.5f * (p0.y + q0.y) * sW8[1];
        d += 0.5f * (p0.z + q0.z) * sW8[2];
        d += 0.5f * (p0.w + q0.w) * sW8[3];
        d += 0.5f * (p1.x + q1.x) * sW8[4];
        d += 0.5f * (p1.y + q1.y) * sW8[5];
        d += 0.5f * (p1.z + q1.z) * sW8[6];
        d += 0.5f * (p1.w + q1.w) * sW8[7];
        d += __shfl_xor_sync(0xffffffffu, d, 1, 16);
        d += __shfl_xor_sync(0xffffffffu, d, 2, 16);
        d += __shfl_xor_sync(0xffffffffu, d, 4, 16);
        d += __shfl_xor_sync(0xffffffffu, d, 8, 16);
        if (u == 0) {
            size_t bs = ((size_t)b * NA + a) * NO;
            float g = 0.0f;
            #pragma unroll
            for (int c = 0; c < 8; c++)
                g += 0.5f * (g_sgl[s1][bs + c] + g_sgl[s2][bs + c]) * sW8[16 + c];
            out[(size_t)b * NA + a] =
                3.14159265358979323846f * (d * (1.0f / 16.0f) + g * (1.0f / 16.0f) + cb);
        }
    }
}

// =============================================================================
extern "C" void kernel_launch(void* const* d_in, const int* in_sizes, int n_in,
                              void* d_out, int out_size)
{
    const float* channel = (const float*)d_in[0];
    const float* W1 = (const float*)d_in[1];
    const float* b1 = (const float*)d_in[2];
    const float* Wm = (const float*)d_in[3];
    const float* bm = (const float*)d_in[4];
    const float* W8 = (const float*)d_in[5];
    const float* b8 = (const float*)d_in[6];
    float* out = (float*)d_out;

    dim3 grdN(16, NB);   // 64-antenna tiles
    dim3 grdW(8, NB);    // 128-antenna tiles
    // L1 -> s0 (= f1), slot set p0 (16 slots)
    k_layer1<<<grdN, 256>>>(channel, W1, b1);
    // L2: s0 -> s1, p0(16) -> p1(8)
    k_mainw<<<grdW, 512>>>(Wm + 0 * 1024, bm + 0 * 32, 0, 1, 0, 1, 16);
    // L3: s1 -> s2 (= f3), p1(8) -> p2(8)
    k_mainw<<<grdW, 512>>>(Wm + 1 * 1024, bm + 1 * 32, 1, 2, 1, 2, 8);
    // L4: s2 -> s1, p2(8) -> p1(8)
    k_mainw<<<grdW, 512>>>(Wm + 2 * 1024, bm + 2 * 32, 2, 1, 2, 1, 8);
    // L5: s1 -> s1 (in-place safe), p1(8) -> p3(8)
    k_mainw<<<grdW, 512>>>(Wm + 3 * 1024, bm + 3 * 32, 1, 1, 1, 3, 8);
    // L6: skip with f1: (s1+s0)/2, (p3[8]+p0[16])/2 -> s0, p1(16 slots)
    k_main_skip<<<grdN, 256>>>(Wm + 4 * 1024, bm + 4 * 32, 1, 0, 0, 3, 0, 1, 8, 16);
    // L7: s0 -> s0, p1(16) -> p0(8)
    k_mainw<<<grdW, 512>>>(Wm + 5 * 1024, bm + 5 * 32, 0, 0, 1, 0, 16);
    // final: (s0 + s2)/2; partial sets p0(8) + p2(8)
    k_final<<<grdN, 256>>>(W8, b8, out, 0, 2, 0, 2, 8);
}

// round 15
// speedup vs baseline: 1.3149x; 1.3149x over previous
#include <cuda_runtime.h>
#include <cuda_bf16.h>

#define NB 128
#define NU 16
#define NA 1024
#define NO 8
#define AT 64
#define NT (NA / AT)

typedef unsigned long long u64;

// ---- persistent scratch (no allocations allowed) ----
__device__ float g_fll[3][(size_t)NB * NA * NU * NO];
__device__ float g_sgl[3][(size_t)NB * NA * NO];
__device__ float g_plg[4][NB * NT * NU * NO];
__device__ float g_pgg[4][NB * NT * NO];
__device__ float g_outp[NB * NA];   // fused-final pointwise partial

__device__ __forceinline__ u64 pack2(float x) {
    u64 r; asm("mov.b64 %0, {%1, %1};" : "=l"(r) : "f"(x)); return r;
}
__device__ __forceinline__ float2 unpack2(u64 v) {
    float2 r; asm("mov.b64 {%0, %1}, %2;" : "=f"(r.x), "=f"(r.y) : "l"(v)); return r;
}
__device__ __forceinline__ u64 repack(float x, float y) {
    u64 r; asm("mov.b64 %0, {%1, %2};" : "=l"(r) : "f"(x), "f"(y)); return r;
}
#define FMA2(d, a, b, c) asm("fma.rn.f32x2 %0, %1, %2, %3;" : "=l"(d) : "l"(a), "l"(b), "l"(c))
#define ADD2(d, a, b)    asm("add.rn.f32x2 %0, %1, %2;"     : "=l"(d) : "l"(a), "l"(b))

__device__ __forceinline__ u64 relu2(u64 x) {
    float2 p = unpack2(x);
    return repack(fmaxf(p.x, 0.0f), fmaxf(p.y, 0.0f));
}
__device__ __forceinline__ u64 shfl64(u64 v, int m) {
    return __shfl_xor_sync(0xffffffffu, v, m);
}

// =============================================================================
// R5 branch core: 256 threads, 4 points/thread, packed FMA + packed epilogues.
// =============================================================================
template <int CIN, int BSTR, bool ADDA>
__device__ __forceinline__ void branch_full(
    int b, int tile, int tid, const float (*v)[CIN],
    const float* __restrict__ sW,
    const float* __restrict__ sAddU, const float* __restrict__ sAddA,
    float* __restrict__ fll_out, float* __restrict__ sgl_out,
    float* __restrict__ sRedLg, float* __restrict__ sRedGg)
{
    const int u = tid & 15, alq = tid >> 4, warp = tid >> 5, lane = tid & 31;

    #pragma unroll
    for (int br = 0; br < 4; br++) {
        const ulonglong2* aup = (const ulonglong2*)(sAddU + (br * 16 + u) * 8);
        const ulonglong2 au0 = aup[0], au1 = aup[1];
        u64 z2[4][4];
        #pragma unroll
        for (int i = 0; i < 4; i++) {
            if (ADDA) {
                const ulonglong2* ap =
                    (const ulonglong2*)(sAddA + (br * 64 + alq + 16 * i) * 8);
                ulonglong2 a0 = ap[0], a1 = ap[1];
                ADD2(z2[i][0], au0.x, a0.x);
                ADD2(z2[i][1], au0.y, a0.y);
                ADD2(z2[i][2], au1.x, a1.x);
                ADD2(z2[i][3], au1.y, a1.y);
            } else {
                z2[i][0] = au0.x; z2[i][1] = au0.y;
                z2[i][2] = au1.x; z2[i][3] = au1.y;
            }
        }
        #pragma unroll
        for (int c = 0; c < CIN; c++) {
            const ulonglong2* wp = (const ulonglong2*)(sW + (br * BSTR + c) * 8);
            const ulonglong2 w0 = wp[0], w1 = wp[1];
            #pragma unroll
            for (int i = 0; i < 4; i++) {
                u64 v2 = pack2(v[i][c]);
                FMA2(z2[i][0], v2, w0.x, z2[i][0]);
                FMA2(z2[i][1], v2, w0.y, z2[i][1]);
                FMA2(z2[i][2], v2, w1.x, z2[i][2]);
                FMA2(z2[i][3], v2, w1.y, z2[i][3]);
            }
        }
        #pragma unroll
        for (int i = 0; i < 4; i++)
            #pragma unroll
            for (int j = 0; j < 4; j++)
                z2[i][j] = relu2(z2[i][j]);

        if (br == 0) {
            #pragma unroll
            for (int i = 0; i < 4; i++) {
                int a = tile * AT + alq + 16 * i;
                size_t idx = (((size_t)b * NA + a) * NU + u) * NO;
                ulonglong2 r0, r1;
                r0.x = z2[i][0]; r0.y = z2[i][1];
                r1.x = z2[i][2]; r1.y = z2[i][3];
                *(ulonglong2*)(fll_out + idx)     = r0;
                *(ulonglong2*)(fll_out + idx + 4) = r1;
            }
        } else if (br == 1) {
            u64 acc[4];
            #pragma unroll
            for (int j = 0; j < 4; j++) {
                u64 t0, t1;
                ADD2(t0, z2[0][j], z2[1][j]);
                ADD2(t1, z2[2][j], z2[3][j]);
                ADD2(acc[j], t0, t1);
            }
            const bool hA = (lane & 16);
            u64 sa = hA ? acc[0] : acc[2];
            u64 sb = hA ? acc[1] : acc[3];
            u64 ka = hA ? acc[2] : acc[0];
            u64 kb = hA ? acc[3] : acc[1];
            u64 ra = shfl64(sa, 16), rb = shfl64(sb, 16);
            ADD2(ka, ka, ra); ADD2(kb, kb, rb);
            ulonglong2 st; st.x = ka; st.y = kb;
            *(ulonglong2*)(sRedLg + warp * 128 + u * 8 + (hA ? 4 : 0)) = st;
        } else if (br == 2) {
            const bool h8 = (u & 8), h4 = (u & 4), h2 = (u & 2);
            #pragma unroll
            for (int i = 0; i < 4; i++) {
                u64 sa = h8 ? z2[i][0] : z2[i][2];
                u64 sb = h8 ? z2[i][1] : z2[i][3];
                u64 ka = h8 ? z2[i][2] : z2[i][0];
                u64 kb = h8 ? z2[i][3] : z2[i][1];
                u64 ra = shfl64(sa, 8), rb = shfl64(sb, 8);
                ADD2(ka, ka, ra); ADD2(kb, kb, rb);
                u64 s1 = h4 ? ka : kb, k1 = h4 ? kb : ka;
                u64 r1 = shfl64(s1, 4);
                ADD2(k1, k1, r1);
                float2 p = unpack2(k1);
                float snd = h2 ? p.x : p.y;
                float t = (h2 ? p.y : p.x) + __shfl_xor_sync(0xffffffffu, snd, 2);
                t += __shfl_xor_sync(0xffffffffu, t, 1);
                if (!(u & 1)) {
                    int o = (h8 ? 4 : 0) + (h4 ? 2 : 0) + (h2 ? 1 : 0);
                    int a = tile * AT + alq + 16 * i;
                    sgl_out[((size_t)b * NA + a) * NO + o] = t;
                }
            }
        } else {
            u64 acc[4];
            #pragma unroll
            for (int j = 0; j < 4; j++) {
                u64 t0, t1;
                ADD2(t0, z2[0][j], z2[1][j]);
                ADD2(t1, z2[2][j], z2[3][j]);
                ADD2(acc[j], t0, t1);
            }
            const bool b0 = (lane & 1), b1 = (lane & 2), b2 = (lane & 4);
            u64 sa = b0 ? acc[0] : acc[2];
            u64 sb = b0 ? acc[1] : acc[3];
            u64 ka = b0 ? acc[2] : acc[0];
            u64 kb = b0 ? acc[3] : acc[1];
            u64 ra = shfl64(sa, 1), rb = shfl64(sb, 1);
            ADD2(ka, ka, ra); ADD2(kb, kb, rb);
            u64 s1 = b1 ? ka : kb, k1 = b1 ? kb : ka;
            u64 r1 = shfl64(s1, 2);
            ADD2(k1, k1, r1);
            float2 p = unpack2(k1);
            float snd = b2 ? p.x : p.y;
            float t = (b2 ? p.y : p.x) + __shfl_xor_sync(0xffffffffu, snd, 4);
            t += __shfl_xor_sync(0xffffffffu, t, 8);
            t += __shfl_xor_sync(0xffffffffu, t, 16);
            if (lane < 8) {
                int o = (b0 ? 4 : 0) + (b1 ? 2 : 0) + (b2 ? 1 : 0);
                sRedGg[warp * 8 + o] = t;
            }
        }
    }
}

__device__ __forceinline__ void write_partials(int b, int tile, int tid, int po,
    const float* __restrict__ sRedLg, const float* __restrict__ sRedGg)
{
    if (tid < 128) {
        float s = 0.0f;
        #pragma unroll
        for (int w = 0; w < 8; w++) s += sRedLg[w * 128 + tid];
        g_plg[po][(b * NT + tile) * 128 + tid] = s;
    }
    if (tid < 8) {
        float s = 0.0f;
        #pragma unroll
        for (int w = 0; w < 8; w++) s += sRedGg[w * 8 + tid];
        g_pgg[po][(b * NT + tile) * 8 + tid] = s;
    }
}

// =============================================================================
// Layer 1 (R5 verbatim)
// =============================================================================
__global__ void __launch_bounds__(256)
k_layer1(const float* __restrict__ ch, const float* __restrict__ W1,
         const float* __restrict__ b1)
{
    __shared__ float sCh[4 * 16 * 65];
    __shared__ float sW[128], sAddU[512];
    __shared__ float sRedLg[1024], sRedGg[64];
    const int tile = blockIdx.x, b = blockIdx.y, tid = threadIdx.x;

    for (int e = tid; e < 4096; e += 256) {
        int c = e >> 10, uu = (e >> 6) & 15, al = e & 63;
        sCh[c * 1040 + uu * 65 + al] =
            ch[(((size_t)b * 4 + c) * NU + uu) * NA + (size_t)tile * AT + al];
    }
    if (tid < 128) sW[tid] = W1[tid];
    #pragma unroll
    for (int k = 0; k < 2; k++) {
        int e = tid + 256 * k, br = e >> 7, o = e & 7;
        sAddU[e] = b1[br * 8 + o];
    }
    __syncthreads();

    const int u = tid & 15, alq = tid >> 4;
    float v[4][4];
    #pragma unroll
    for (int i = 0; i < 4; i++)
        #pragma unroll
        for (int c = 0; c < 4; c++)
            v[i][c] = sCh[c * 1040 + u * 65 + alq + 16 * i];

    branch_full<4, 4, false>(b, tile, tid, v, sW, sAddU, nullptr,
                             g_fll[0], g_sgl[0], sRedLg, sRedGg);
    __syncthreads();
    write_partials(b, tile, tid, 0, sRedLg, sRedGg);
}

// =============================================================================
// Middle layers 2..6 (R5 verbatim)
// =============================================================================
template <bool SKIP>
__global__ void __launch_bounds__(256)
k_main(const float* __restrict__ W, const float* __restrict__ bias,
       int si, int si2, int so, int pi, int pi2, int po)
{
    __shared__ float sW[1024], sAddU[512], sAddA[2048];
    __shared__ float sSgl[512], sFlg[128], sFgg[8];
    __shared__ float sRedLg[1024], sRedGg[64];
    const int tile = blockIdx.x, b = blockIdx.y, tid = threadIdx.x;
    const int u = tid & 15, alq = tid >> 4;

    const float* __restrict__ fin  = g_fll[si];
    const float* __restrict__ fin2 = g_fll[si2];
    float4 vp[4][2], vq[4][2];
    #pragma unroll
    for (int i = 0; i < 4; i++) {
        int a = tile * AT + alq + 16 * i;
        size_t idx = (((size_t)b * NA + a) * NU + u) * NO;
        vp[i][0] = *(const float4*)(fin + idx);
        vp[i][1] = *(const float4*)(fin + idx + 4);
        if (SKIP) {
            vq[i][0] = *(const float4*)(fin2 + idx);
            vq[i][1] = *(const float4*)(fin2 + idx + 4);
        }
    }

    ((float4*)sW)[tid] = ((const float4*)W)[tid];
    if (tid < 128) {
        size_t base = ((size_t)b * NA + (size_t)tile * AT) * NO;
        float4 p = ((const float4*)(g_sgl[si] + base))[tid];
        if (SKIP) {
            float4 q = ((const float4*)(g_sgl[si2] + base))[tid];
            p.x = 0.5f * (p.x + q.x); p.y = 0.5f * (p.y + q.y);
            p.z = 0.5f * (p.z + q.z); p.w = 0.5f * (p.w + q.w);
        }
        ((float4*)sSgl)[tid] = p;

        float s = 0.0f;
        #pragma unroll
        for (int t = 0; t < NT; t++) s += g_plg[pi][(b * NT + t) * 128 + tid];
        if (SKIP) {
            float s2 = 0.0f;
            #pragma unroll
            for (int t = 0; t < NT; t++) s2 += g_plg[pi2][(b * NT + t) * 128 + tid];
            s = 0.5f * (s + s2);
        }
        sFlg[tid] = s * (1.0f / NA);
    }
    if (tid < 8) {
        float s = 0.0f;
        #pragma unroll
        for (int t = 0; t < NT; t++) s += g_pgg[pi][(b * NT + t) * 8 + tid];
        if (SKIP) {
            float s2 = 0.0f;
            #pragma unroll
            for (int t = 0; t < NT; t++) s2 += g_pgg[pi2][(b * NT + t) * 8 + tid];
            s = 0.5f * (s + s2);
        }
        sFgg[tid] = s * (1.0f / (NA * NU));
    }
    __syncthreads();

    #pragma unroll
    for (int k = 0; k < 2; k++) {
        int e = tid + 256 * k, br = e >> 7, uu = (e >> 3) & 15, o = e & 7;
        float acc = bias[br * 8 + o];
        #pragma unroll
        for (int c = 0; c < 8; c++) {
            acc += sFgg[c]          * sW[(br * 32 + 24 + c) * 8 + o];
            acc += sFlg[uu * 8 + c] * sW[(br * 32 +  8 + c) * 8 + o];
        }
        sAddU[e] = acc;
    }
    #pragma unroll
    for (int k = 0; k < 8; k++) {
        int e = tid + 256 * k, br = e >> 9, al = (e >> 3) & 63, o = e & 7;
        float acc = 0.0f;
        #pragma unroll
        for (int c = 0; c < 8; c++)
            acc += sSgl[al * 8 + c] * sW[(br * 32 + 16 + c) * 8 + o];
        sAddA[e] = acc * (1.0f / 16.0f);
    }
    __syncthreads();

    float v[4][8];
    #pragma unroll
    for (int i = 0; i < 4; i++) {
        float4 p0 = vp[i][0], p1 = vp[i][1];
        if (SKIP) {
            float4 q0 = vq[i][0], q1 = vq[i][1];
            p0.x = 0.5f * (p0.x + q0.x); p0.y = 0.5f * (p0.y + q0.y);
            p0.z = 0.5f * (p0.z + q0.z); p0.w = 0.5f * (p0.w + q0.w);
            p1.x = 0.5f * (p1.x + q1.x); p1.y = 0.5f * (p1.y + q1.y);
            p1.z = 0.5f * (p1.z + q1.z); p1.w = 0.5f * (p1.w + q1.w);
        }
        v[i][0] = p0.x; v[i][1] = p0.y; v[i][2] = p0.z; v[i][3] = p0.w;
        v[i][4] = p1.x; v[i][5] = p1.y; v[i][6] = p1.z; v[i][7] = p1.w;
    }

    branch_full<8, 32, true>(b, tile, tid, v, sW, sAddU, sAddA,
                             g_fll[so], g_sgl[so], sRedLg, sRedGg);
    __syncthreads();
    write_partials(b, tile, tid, po, sRedLg, sRedGg);
}

// =============================================================================
// Layer 7 fused with the final's pointwise work.
//   Inputs: fll/sgl state s7i (=0), plg/pgg slots p7i (=1); skip state sF (=2).
//   Outputs: partials slot p7o (=0) for cb, and
//            g_outp[b,a] = d/16 + g/16  (d = final ll-dot, g = final gl-dot).
//   No fll/sgl global stores (k_final was their only consumer).
// =============================================================================
__global__ void __launch_bounds__(256)
k_last(const float* __restrict__ W, const float* __restrict__ bias,
       const float* __restrict__ W8)
{
    const int s7i = 0, p7i = 1, p7o = 0, sF = 2;
    __shared__ float sW[1024], sAddU[512], sAddA[2048];
    __shared__ float sSgl[512], sSgl2[512], sFlg[128], sFgg[8];
    __shared__ float sRedLg[1024], sRedGg[64];
    __shared__ float sW8[32], sGl[512], sDD[64];
    const int tile = blockIdx.x, b = blockIdx.y, tid = threadIdx.x;
    const int u = tid & 15, alq = tid >> 4, warp = tid >> 5, lane = tid & 31;

    // ---- prefetch v (layer input, s0) and skip tensor (s2) pre-barrier ----
    const float* __restrict__ fin  = g_fll[s7i];
    const float* __restrict__ fin2 = g_fll[sF];
    float4 vp[4][2], vq[4][2];
    #pragma unroll
    for (int i = 0; i < 4; i++) {
        int a = tile * AT + alq + 16 * i;
        size_t idx = (((size_t)b * NA + a) * NU + u) * NO;
        vp[i][0] = *(const float4*)(fin + idx);
        vp[i][1] = *(const float4*)(fin + idx + 4);
        vq[i][0] = *(const float4*)(fin2 + idx);
        vq[i][1] = *(const float4*)(fin2 + idx + 4);
    }

    // ---- prologue ----
    ((float4*)sW)[tid] = ((const float4*)W)[tid];
    if (tid < 32) sW8[tid] = W8[tid];
    if (tid < 128) {
        size_t base = ((size_t)b * NA + (size_t)tile * AT) * NO;
        ((float4*)sSgl)[tid]  = ((const float4*)(g_sgl[s7i] + base))[tid];
        ((float4*)sSgl2)[tid] = ((const float4*)(g_sgl[sF]  + base))[tid];

        float s = 0.0f;
        #pragma unroll
        for (int t = 0; t < NT; t++) s += g_plg[p7i][(b * NT + t) * 128 + tid];
        sFlg[tid] = s * (1.0f / NA);
    }
    if (tid < 8) {
        float s = 0.0f;
        #pragma unroll
        for (int t = 0; t < NT; t++) s += g_pgg[p7i][(b * NT + t) * 8 + tid];
        sFgg[tid] = s * (1.0f / (NA * NU));
    }
    __syncthreads();

    #pragma unroll
    for (int k = 0; k < 2; k++) {
        int e = tid + 256 * k, br = e >> 7, uu = (e >> 3) & 15, o = e & 7;
        float acc = bias[br * 8 + o];
        #pragma unroll
        for (int c = 0; c < 8; c++) {
            acc += sFgg[c]          * sW[(br * 32 + 24 + c) * 8 + o];
            acc += sFlg[uu * 8 + c] * sW[(br * 32 +  8 + c) * 8 + o];
        }
        sAddU[e] = acc;
    }
    #pragma unroll
    for (int k = 0; k < 8; k++) {
        int e = tid + 256 * k, br = e >> 9, al = (e >> 3) & 63, o = e & 7;
        float acc = 0.0f;
        #pragma unroll
        for (int c = 0; c < 8; c++)
            acc += sSgl[al * 8 + c] * sW[(br * 32 + 16 + c) * 8 + o];
        sAddA[e] = acc * (1.0f / 16.0f);
    }
    __syncthreads();

    float v[4][8];
    #pragma unroll
    for (int i = 0; i < 4; i++) {
        float4 p0 = vp[i][0], p1 = vp[i][1];
        v[i][0] = p0.x; v[i][1] = p0.y; v[i][2] = p0.z; v[i][3] = p0.w;
        v[i][4] = p1.x; v[i][5] = p1.y; v[i][6] = p1.z; v[i][7] = p1.w;
    }
    // skip tensor, packed pairs for the d-dot
    u64 q2[4][4];
    #pragma unroll
    for (int i = 0; i < 4; i++) {
        q2[i][0] = repack(vq[i][0].x, vq[i][0].y);
        q2[i][1] = repack(vq[i][0].z, vq[i][0].w);
        q2[i][2] = repack(vq[i][1].x, vq[i][1].y);
        q2[i][3] = repack(vq[i][1].z, vq[i][1].w);
    }
    const ulonglong2* w8p = (const ulonglong2*)sW8;
    const ulonglong2 w8a = w8p[0], w8b = w8p[1];

    // ---- mainloop (branch_full specialized: br0 -> d-dot, br2 -> smem) ----
    #pragma unroll
    for (int br = 0; br < 4; br++) {
        const ulonglong2* aup = (const ulonglong2*)(sAddU + (br * 16 + u) * 8);
        const ulonglong2 au0 = aup[0], au1 = aup[1];
        u64 z2[4][4];
        #pragma unroll
        for (int i = 0; i < 4; i++) {
            const ulonglong2* ap =
                (const ulonglong2*)(sAddA + (br * 64 + alq + 16 * i) * 8);
            ulonglong2 a0 = ap[0], a1 = ap[1];
            ADD2(z2[i][0], au0.x, a0.x);
            ADD2(z2[i][1], au0.y, a0.y);
            ADD2(z2[i][2], au1.x, a1.x);
            ADD2(z2[i][3], au1.y, a1.y);
        }
        #pragma unroll
        for (int c = 0; c < 8; c++) {
            const ulonglong2* wp = (const ulonglong2*)(sW + (br * 32 + c) * 8);
            const ulonglong2 w0 = wp[0], w1 = wp[1];
            #pragma unroll
            for (int i = 0; i < 4; i++) {
                u64 v2 = pack2(v[i][c]);
                FMA2(z2[i][0], v2, w0.x, z2[i][0]);
                FMA2(z2[i][1], v2, w0.y, z2[i][1]);
                FMA2(z2[i][2], v2, w1.x, z2[i][2]);
                FMA2(z2[i][3], v2, w1.y, z2[i][3]);
            }
        }
        #pragma unroll
        for (int i = 0; i < 4; i++)
            #pragma unroll
            for (int j = 0; j < 4; j++)
                z2[i][j] = relu2(z2[i][j]);

        if (br == 0) {            // ll -> final d-dot, u-reduce, stash per a
            #pragma unroll
            for (int i = 0; i < 4; i++) {
                u64 acc2 = 0, t;
                ADD2(t, z2[i][0], q2[i][0]); FMA2(acc2, t, w8a.x, acc2);
                ADD2(t, z2[i][1], q2[i][1]); FMA2(acc2, t, w8a.y, acc2);
                ADD2(t, z2[i][2], q2[i][2]); FMA2(acc2, t, w8b.x, acc2);
                ADD2(t, z2[i][3], q2[i][3]); FMA2(acc2, t, w8b.y, acc2);
                float2 p = unpack2(acc2);
                float dd = 0.5f * (p.x + p.y);
                dd += __shfl_xor_sync(0xffffffffu, dd, 1, 16);
                dd += __shfl_xor_sync(0xffffffffu, dd, 2, 16);
                dd += __shfl_xor_sync(0xffffffffu, dd, 4, 16);
                dd += __shfl_xor_sync(0xffffffffu, dd, 8, 16);
                if (u == 0) sDD[alq + 16 * i] = dd;
            }
        } else if (br == 1) {
            u64 acc[4];
            #pragma unroll
            for (int j = 0; j < 4; j++) {
                u64 t0, t1;
                ADD2(t0, z2[0][j], z2[1][j]);
                ADD2(t1, z2[2][j], z2[3][j]);
                ADD2(acc[j], t0, t1);
            }
            const bool hA = (lane & 16);
            u64 sa = hA ? acc[0] : acc[2];
            u64 sb = hA ? acc[1] : acc[3];
            u64 ka = hA ? acc[2] : acc[0];
            u64 kb = hA ? acc[3] : acc[1];
            u64 ra = shfl64(sa, 16), rb = shfl64(sb, 16);
            ADD2(ka, ka, ra); ADD2(kb, kb, rb);
            ulonglong2 st; st.x = ka; st.y = kb;
            *(ulonglong2*)(sRedLg + warp * 128 + u * 8 + (hA ? 4 : 0)) = st;
        } else if (br == 2) {     // gl -> smem (final g-dot consumes it)
            const bool h8 = (u & 8), h4 = (u & 4), h2 = (u & 2);
            #pragma unroll
            for (int i = 0; i < 4; i++) {
                u64 sa = h8 ? z2[i][0] : z2[i][2];
                u64 sb = h8 ? z2[i][1] : z2[i][3];
                u64 ka = h8 ? z2[i][2] : z2[i][0];
                u64 kb = h8 ? z2[i][3] : z2[i][1];
                u64 ra = shfl64(sa, 8), rb = shfl64(sb, 8);
                ADD2(ka, ka, ra); ADD2(kb, kb, rb);
                u64 s1 = h4 ? ka : kb, k1 = h4 ? kb : ka;
                u64 r1 = shfl64(s1, 4);
                ADD2(k1, k1, r1);
                float2 p = unpack2(k1);
                float snd = h2 ? p.x : p.y;
                float t = (h2 ? p.y : p.x) + __shfl_xor_sync(0xffffffffu, snd, 2);
                t += __shfl_xor_sync(0xffffffffu, t, 1);
                if (!(u & 1)) {
                    int o = (h8 ? 4 : 0) + (h4 ? 2 : 0) + (h2 ? 1 : 0);
                    sGl[(alq + 16 * i) * 8 + o] = t;
                }
            }
        } else {
            u64 acc[4];
            #pragma unroll
            for (int j = 0; j < 4; j++) {
                u64 t0, t1;
                ADD2(t0, z2[0][j], z2[1][j]);
                ADD2(t1, z2[2][j], z2[3][j]);
                ADD2(acc[j], t0, t1);
            }
            const bool b0 = (lane & 1), b1 = (lane & 2), b2 = (lane & 4);
            u64 sa = b0 ? acc[0] : acc[2];
            u64 sb = b0 ? acc[1] : acc[3];
            u64 ka = b0 ? acc[2] : acc[0];
            u64 kb = b0 ? acc[3] : acc[1];
            u64 ra = shfl64(sa, 1), rb = shfl64(sb, 1);
            ADD2(ka, ka, ra); ADD2(kb, kb, rb);
            u64 s1 = b1 ? ka : kb, k1 = b1 ? kb : ka;
            u64 r1 = shfl64(s1, 2);
            ADD2(k1, k1, r1);
            float2 p = unpack2(k1);
            float snd = b2 ? p.x : p.y;
            float t = (b2 ? p.y : p.x) + __shfl_xor_sync(0xffffffffu, snd, 4);
            t += __shfl_xor_sync(0xffffffffu, t, 8);
            t += __shfl_xor_sync(0xffffffffu, t, 16);
            if (lane < 8) {
                int o = (b0 ? 4 : 0) + (b1 ? 2 : 0) + (b2 ? 1 : 0);
                sRedGg[warp * 8 + o] = t;
            }
        }
    }
    __syncthreads();
    write_partials(b, tile, tid, p7o, sRedLg, sRedGg);
    // final pointwise partial: outp = d/16 + g/16
    if (tid < 64) {
        int al = tid, a = tile * AT + al;
        float g = 0.0f;
        #pragma unroll
        for (int c = 0; c < 8; c++)
            g += 0.5f * (sGl[al * 8 + c] + sSgl2[al * 8 + c]) * sW8[16 + c];
        g_outp[b * NA + a] = (sDD[al] + g) * (1.0f / 16.0f);
    }
}

// =============================================================================
// Tiny final: out[b,a] = pi * (outp[b,a] + cb(b)).  One CTA per b.
// =============================================================================
__global__ void __launch_bounds__(256)
k_fin2(const float* __restrict__ W8, const float* __restrict__ b8,
       float* __restrict__ out, int p1, int p2)
{
    __shared__ float sW8[32];
    __shared__ float sFlg[128], sFgg[8];
    __shared__ float cU[17];
    const int b = blockIdx.x, tid = threadIdx.x;
    if (tid < 32) sW8[tid] = W8[tid];
    if (tid < 128) {
        float s = 0.0f;
        #pragma unroll
        for (int t = 0; t < NT; t++)
            s += g_plg[p1][(b * NT + t) * 128 + tid] +
                 g_plg[p2][(b * NT + t) * 128 + tid];
        sFlg[tid] = s * (0.5f / NA);
    }
    if (tid < 8) {
        float s = 0.0f;
        #pragma unroll
        for (int t = 0; t < NT; t++)
            s += g_pgg[p1][(b * NT + t) * 8 + tid] +
                 g_pgg[p2][(b * NT + t) * 8 + tid];
        sFgg[tid] = s * (0.5f / (NA * NU));
    }
    __syncthreads();
    if (tid < 16) {
        float s = 0.0f;
        #pragma unroll
        for (int c = 0; c < 8; c++)
            s += sFlg[tid * 8 + c] * sW8[8 + c];
        cU[tid] = s;
    }
    __syncthreads();
    if (tid == 0) {
        float s = 0.0f;
        for (int uu = 0; uu < 16; uu++) s += cU[uu];
        s *= (1.0f / 16.0f);
        #pragma unroll
        for (int c = 0; c < 8; c++) s += sFgg[c] * sW8[24 + c];
        s += b8[0];
        cU[16] = s;
    }
    __syncthreads();
    const float cb = cU[16];
    #pragma unroll
    for (int k = 0; k < 4; k++) {
        int a = tid + 256 * k;
        out[(size_t)b * NA + a] =
            3.14159265358979323846f * (g_outp[b * NA + a] + cb);
    }
}

// =============================================================================
extern "C" void kernel_launch(void* const* d_in, const int* in_sizes, int n_in,
                              void* d_out, int out_size)
{
    const float* channel = (const float*)d_in[0];
    const float* W1 = (const float*)d_in[1];
    const float* b1 = (const float*)d_in[2];
    const float* Wm = (const float*)d_in[3];
    const float* bm = (const float*)d_in[4];
    const float* W8 = (const float*)d_in[5];
    const float* b8 = (const float*)d_in[6];
    float* out = (float*)d_out;

    dim3 grd(NT, NB);
    k_layer1<<<grd, 256>>>(channel, W1, b1);
    k_main<false><<<grd, 256>>>(Wm + 0 * 1024, bm + 0 * 32, 0, 0, 1, 0, 0, 1);
    k_main<false><<<grd, 256>>>(Wm + 1 * 1024, bm + 1 * 32, 1, 1, 2, 1, 1, 2);
    k_main<false><<<grd, 256>>>(Wm + 2 * 1024, bm + 2 * 32, 2, 2, 1, 2, 2, 1);
    k_main<false><<<grd, 256>>>(Wm + 3 * 1024, bm + 3 * 32, 1, 1, 1, 1, 1, 3);
    k_main<true><<<grd, 256>>>(Wm + 4 * 1024, bm + 4 * 32, 1, 0, 0, 3, 0, 1);
    // L7 fused with final pointwise work: s0/p1 in, partials p0 + outp out
    k_last<<<grd, 256>>>(Wm + 5 * 1024, bm + 5 * 32, W8);
    // final constant add: cb from (p0, p2)
    k_fin2<<<NB, 256>>>(W8, b8, out, 0, 2);
}

// round 16
// speedup vs baseline: 1.3901x; 1.0572x over previous
#include <cuda_runtime.h>
#include <cuda_bf16.h>

#define NB 128
#define NU 16
#define NA 1024
#define NO 8
#define AT 64
#define NT (NA / AT)

typedef unsigned long long u64;

// ---- persistent scratch (no allocations allowed) ----
__device__ float g_fll[3][(size_t)NB * NA * NU * NO];
__device__ float g_sgl[3][(size_t)NB * NA * NO];
__device__ float g_plg[4][NB * NT * NU * NO];
__device__ float g_pgg[4][NB * NT * NO];
__device__ float g_outp[NB * NA];

__device__ __forceinline__ u64 pack2(float x) {
    u64 r; asm("mov.b64 %0, {%1, %1};" : "=l"(r) : "f"(x)); return r;
}
__device__ __forceinline__ float2 unpack2(u64 v) {
    float2 r; asm("mov.b64 {%0, %1}, %2;" : "=f"(r.x), "=f"(r.y) : "l"(v)); return r;
}
__device__ __forceinline__ u64 repack(float x, float y) {
    u64 r; asm("mov.b64 %0, {%1, %2};" : "=l"(r) : "f"(x), "f"(y)); return r;
}
#define FMA2(d, a, b, c) asm("fma.rn.f32x2 %0, %1, %2, %3;" : "=l"(d) : "l"(a), "l"(b), "l"(c))
#define ADD2(d, a, b)    asm("add.rn.f32x2 %0, %1, %2;"     : "=l"(d) : "l"(a), "l"(b))

__device__ __forceinline__ u64 relu2(u64 x) {
    float2 p = unpack2(x);
    return repack(fmaxf(p.x, 0.0f), fmaxf(p.y, 0.0f));
}
__device__ __forceinline__ u64 shfl64(u64 v, int m) {
    return __shfl_xor_sync(0xffffffffu, v, m);
}

// =============================================================================
// Branch core: 256 threads, 4 points/thread, packed FMA + packed epilogues.
// =============================================================================
template <int CIN, int BSTR, bool ADDA>
__device__ __forceinline__ void branch_full(
    int b, int tile, int tid, const float (*v)[CIN],
    const float* __restrict__ sW,
    const float* __restrict__ sAddU, const float* __restrict__ sAddA,
    float* __restrict__ fll_out, float* __restrict__ sgl_out,
    float* __restrict__ sRedLg, float* __restrict__ sRedGg)
{
    const int u = tid & 15, alq = tid >> 4, warp = tid >> 5, lane = tid & 31;

    #pragma unroll
    for (int br = 0; br < 4; br++) {
        const ulonglong2* aup = (const ulonglong2*)(sAddU + (br * 16 + u) * 8);
        const ulonglong2 au0 = aup[0], au1 = aup[1];
        u64 z2[4][4];
        #pragma unroll
        for (int i = 0; i < 4; i++) {
            if (ADDA) {
                const ulonglong2* ap =
                    (const ulonglong2*)(sAddA + (br * 64 + alq + 16 * i) * 8);
                ulonglong2 a0 = ap[0], a1 = ap[1];
                ADD2(z2[i][0], au0.x, a0.x);
                ADD2(z2[i][1], au0.y, a0.y);
                ADD2(z2[i][2], au1.x, a1.x);
                ADD2(z2[i][3], au1.y, a1.y);
            } else {
                z2[i][0] = au0.x; z2[i][1] = au0.y;
                z2[i][2] = au1.x; z2[i][3] = au1.y;
            }
        }
        #pragma unroll
        for (int c = 0; c < CIN; c++) {
            const ulonglong2* wp = (const ulonglong2*)(sW + (br * BSTR + c) * 8);
            const ulonglong2 w0 = wp[0], w1 = wp[1];
            #pragma unroll
            for (int i = 0; i < 4; i++) {
                u64 v2 = pack2(v[i][c]);
                FMA2(z2[i][0], v2, w0.x, z2[i][0]);
                FMA2(z2[i][1], v2, w0.y, z2[i][1]);
                FMA2(z2[i][2], v2, w1.x, z2[i][2]);
                FMA2(z2[i][3], v2, w1.y, z2[i][3]);
            }
        }
        #pragma unroll
        for (int i = 0; i < 4; i++)
            #pragma unroll
            for (int j = 0; j < 4; j++)
                z2[i][j] = relu2(z2[i][j]);

        if (br == 0) {
            #pragma unroll
            for (int i = 0; i < 4; i++) {
                int a = tile * AT + alq + 16 * i;
                size_t idx = (((size_t)b * NA + a) * NU + u) * NO;
                ulonglong2 r0, r1;
                r0.x = z2[i][0]; r0.y = z2[i][1];
                r1.x = z2[i][2]; r1.y = z2[i][3];
                *(ulonglong2*)(fll_out + idx)     = r0;
                *(ulonglong2*)(fll_out + idx + 4) = r1;
            }
        } else if (br == 1) {
            u64 acc[4];
            #pragma unroll
            for (int j = 0; j < 4; j++) {
                u64 t0, t1;
                ADD2(t0, z2[0][j], z2[1][j]);
                ADD2(t1, z2[2][j], z2[3][j]);
                ADD2(acc[j], t0, t1);
            }
            const bool hA = (lane & 16);
            u64 sa = hA ? acc[0] : acc[2];
            u64 sb = hA ? acc[1] : acc[3];
            u64 ka = hA ? acc[2] : acc[0];
            u64 kb = hA ? acc[3] : acc[1];
            u64 ra = shfl64(sa, 16), rb = shfl64(sb, 16);
            ADD2(ka, ka, ra); ADD2(kb, kb, rb);
            ulonglong2 st; st.x = ka; st.y = kb;
            *(ulonglong2*)(sRedLg + warp * 128 + u * 8 + (hA ? 4 : 0)) = st;
        } else if (br == 2) {
            const bool h8 = (u & 8), h4 = (u & 4), h2 = (u & 2);
            #pragma unroll
            for (int i = 0; i < 4; i++) {
                u64 sa = h8 ? z2[i][0] : z2[i][2];
                u64 sb = h8 ? z2[i][1] : z2[i][3];
                u64 ka = h8 ? z2[i][2] : z2[i][0];
                u64 kb = h8 ? z2[i][3] : z2[i][1];
                u64 ra = shfl64(sa, 8), rb = shfl64(sb, 8);
                ADD2(ka, ka, ra); ADD2(kb, kb, rb);
                u64 s1 = h4 ? ka : kb, k1 = h4 ? kb : ka;
                u64 r1 = shfl64(s1, 4);
                ADD2(k1, k1, r1);
                float2 p = unpack2(k1);
                float snd = h2 ? p.x : p.y;
                float t = (h2 ? p.y : p.x) + __shfl_xor_sync(0xffffffffu, snd, 2);
                t += __shfl_xor_sync(0xffffffffu, t, 1);
                if (!(u & 1)) {
                    int o = (h8 ? 4 : 0) + (h4 ? 2 : 0) + (h2 ? 1 : 0);
                    int a = tile * AT + alq + 16 * i;
                    sgl_out[((size_t)b * NA + a) * NO + o] = t;
                }
            }
        } else {
            u64 acc[4];
            #pragma unroll
            for (int j = 0; j < 4; j++) {
                u64 t0, t1;
                ADD2(t0, z2[0][j], z2[1][j]);
                ADD2(t1, z2[2][j], z2[3][j]);
                ADD2(acc[j], t0, t1);
            }
            const bool b0 = (lane & 1), b1 = (lane & 2), b2 = (lane & 4);
            u64 sa = b0 ? acc[0] : acc[2];
            u64 sb = b0 ? acc[1] : acc[3];
            u64 ka = b0 ? acc[2] : acc[0];
            u64 kb = b0 ? acc[3] : acc[1];
            u64 ra = shfl64(sa, 1), rb = shfl64(sb, 1);
            ADD2(ka, ka, ra); ADD2(kb, kb, rb);
            u64 s1 = b1 ? ka : kb, k1 = b1 ? kb : ka;
            u64 r1 = shfl64(s1, 2);
            ADD2(k1, k1, r1);
            float2 p = unpack2(k1);
            float snd = b2 ? p.x : p.y;
            float t = (b2 ? p.y : p.x) + __shfl_xor_sync(0xffffffffu, snd, 4);
            t += __shfl_xor_sync(0xffffffffu, t, 8);
            t += __shfl_xor_sync(0xffffffffu, t, 16);
            if (lane < 8) {
                int o = (b0 ? 4 : 0) + (b1 ? 2 : 0) + (b2 ? 1 : 0);
                sRedGg[warp * 8 + o] = t;
            }
        }
    }
}

__device__ __forceinline__ void write_partials(int b, int tile, int tid, int po,
    const float* __restrict__ sRedLg, const float* __restrict__ sRedGg)
{
    if (tid < 128) {
        float s = 0.0f;
        #pragma unroll
        for (int w = 0; w < 8; w++) s += sRedLg[w * 128 + tid];
        g_plg[po][(b * NT + tile) * 128 + tid] = s;
    }
    if (tid < 8) {
        float s = 0.0f;
        #pragma unroll
        for (int w = 0; w < 8; w++) s += sRedGg[w * 8 + tid];
        g_pgg[po][(b * NT + tile) * 8 + tid] = s;
    }
}

// =============================================================================
// Layer 1 (R15 verbatim)
// =============================================================================
__global__ void __launch_bounds__(256)
k_layer1(const float* __restrict__ ch, const float* __restrict__ W1,
         const float* __restrict__ b1)
{
    __shared__ float sCh[4 * 16 * 65];
    __shared__ float sW[128], sAddU[512];
    __shared__ float sRedLg[1024], sRedGg[64];
    const int tile = blockIdx.x, b = blockIdx.y, tid = threadIdx.x;

    for (int e = tid; e < 4096; e += 256) {
        int c = e >> 10, uu = (e >> 6) & 15, al = e & 63;
        sCh[c * 1040 + uu * 65 + al] =
            ch[(((size_t)b * 4 + c) * NU + uu) * NA + (size_t)tile * AT + al];
    }
    if (tid < 128) sW[tid] = W1[tid];
    #pragma unroll
    for (int k = 0; k < 2; k++) {
        int e = tid + 256 * k, br = e >> 7, o = e & 7;
        sAddU[e] = b1[br * 8 + o];
    }
    __syncthreads();

    const int u = tid & 15, alq = tid >> 4;
    float v[4][4];
    #pragma unroll
    for (int i = 0; i < 4; i++)
        #pragma unroll
        for (int c = 0; c < 4; c++)
            v[i][c] = sCh[c * 1040 + u * 65 + alq + 16 * i];

    branch_full<4, 4, false>(b, tile, tid, v, sW, sAddU, nullptr,
                             g_fll[0], g_sgl[0], sRedLg, sRedGg);
    __syncthreads();
    write_partials(b, tile, tid, 0, sRedLg, sRedGg);
}

// =============================================================================
// Non-skip middle layer, 3 CTAs/SM. Split v prefetch: points 0-1 held across
// the prologue (16 regs); points 2-3 issued after barrier 1, hidden by the
// addU/addA build. Keeps 4-pt/thread LDS amortization with 24 warps/SM.
// =============================================================================
__global__ void __launch_bounds__(256, 3)
k_main_ns(const float* __restrict__ W, const float* __restrict__ bias,
          int si, int so, int pi, int po)
{
    __shared__ float sW[1024], sAddU[512], sAddA[2048];
    __shared__ float sSgl[512], sFlg[128], sFgg[8];
    __shared__ float sRedLg[1024], sRedGg[64];
    const int tile = blockIdx.x, b = blockIdx.y, tid = threadIdx.x;
    const int u = tid & 15, alq = tid >> 4;

    const float* __restrict__ fin = g_fll[si];
    const unsigned vbase =
        ((unsigned)(b * NA + tile * AT + alq) * NU + u) * NO;

    // ---- prefetch points 0,1 only (16 regs across prologue) ----
    float4 vp[2][2];
    #pragma unroll
    for (int i = 0; i < 2; i++) {
        unsigned idx = vbase + (unsigned)(16 * i) * NU * NO;
        vp[i][0] = *(const float4*)(fin + idx);
        vp[i][1] = *(const float4*)(fin + idx + 4);
    }

    // ---- prologue: stage weights + small components ----
    ((float4*)sW)[tid] = ((const float4*)W)[tid];
    if (tid < 128) {
        size_t base = ((size_t)b * NA + (size_t)tile * AT) * NO;
        ((float4*)sSgl)[tid] = ((const float4*)(g_sgl[si] + base))[tid];

        float s = 0.0f;
        #pragma unroll
        for (int t = 0; t < NT; t++) s += g_plg[pi][(b * NT + t) * 128 + tid];
        sFlg[tid] = s * (1.0f / NA);
    }
    if (tid < 8) {
        float s = 0.0f;
        #pragma unroll
        for (int t = 0; t < NT; t++) s += g_pgg[pi][(b * NT + t) * 8 + tid];
        sFgg[tid] = s * (1.0f / (NA * NU));
    }
    __syncthreads();

    // ---- issue LDGs for points 2,3 (latency hidden by the builds below) ----
    float4 vq[2][2];
    #pragma unroll
    for (int i = 0; i < 2; i++) {
        unsigned idx = vbase + (unsigned)(32 + 16 * i) * NU * NO;
        vq[i][0] = *(const float4*)(fin + idx);
        vq[i][1] = *(const float4*)(fin + idx + 4);
    }

    // addU[br][u][o] = bias + W_lg^T f_lg(u) + W_gg^T f_gg
    #pragma unroll
    for (int k = 0; k < 2; k++) {
        int e = tid + 256 * k, br = e >> 7, uu = (e >> 3) & 15, o = e & 7;
        float acc = bias[br * 8 + o];
        #pragma unroll
        for (int c = 0; c < 8; c++) {
            acc += sFgg[c]          * sW[(br * 32 + 24 + c) * 8 + o];
            acc += sFlg[uu * 8 + c] * sW[(br * 32 +  8 + c) * 8 + o];
        }
        sAddU[e] = acc;
    }
    // addA[br][al][o] = (1/16) W_gl^T S_gl(a)
    #pragma unroll
    for (int k = 0; k < 8; k++) {
        int e = tid + 256 * k, br = e >> 9, al = (e >> 3) & 63, o = e & 7;
        float acc = 0.0f;
        #pragma unroll
        for (int c = 0; c < 8; c++)
            acc += sSgl[al * 8 + c] * sW[(br * 32 + 16 + c) * 8 + o];
        sAddA[e] = acc * (1.0f / 16.0f);
    }
    __syncthreads();

    float v[4][8];
    #pragma unroll
    for (int i = 0; i < 2; i++) {
        v[i][0] = vp[i][0].x; v[i][1] = vp[i][0].y;
        v[i][2] = vp[i][0].z; v[i][3] = vp[i][0].w;
        v[i][4] = vp[i][1].x; v[i][5] = vp[i][1].y;
        v[i][6] = vp[i][1].z; v[i][7] = vp[i][1].w;
        v[i + 2][0] = vq[i][0].x; v[i + 2][1] = vq[i][0].y;
        v[i + 2][2] = vq[i][0].z; v[i + 2][3] = vq[i][0].w;
        v[i + 2][4] = vq[i][1].x; v[i + 2][5] = vq[i][1].y;
        v[i + 2][6] = vq[i][1].z; v[i + 2][7] = vq[i][1].w;
    }

    branch_full<8, 32, true>(b, tile, tid, v, sW, sAddU, sAddA,
                             g_fll[so], g_sgl[so], sRedLg, sRedGg);
    __syncthreads();
    write_partials(b, tile, tid, po, sRedLg, sRedGg);
}

// =============================================================================
// SKIP middle layer (R15 2-CTA path, full prefetch)
// =============================================================================
__global__ void __launch_bounds__(256)
k_main_skip(const float* __restrict__ W, const float* __restrict__ bias,
            int si, int si2, int so, int pi, int pi2, int po)
{
    __shared__ float sW[1024], sAddU[512], sAddA[2048];
    __shared__ float sSgl[512], sFlg[128], sFgg[8];
    __shared__ float sRedLg[1024], sRedGg[64];
    const int tile = blockIdx.x, b = blockIdx.y, tid = threadIdx.x;
    const int u = tid & 15, alq = tid >> 4;

    const float* __restrict__ fin  = g_fll[si];
    const float* __restrict__ fin2 = g_fll[si2];
    float4 vp[4][2], vq[4][2];
    #pragma unroll
    for (int i = 0; i < 4; i++) {
        int a = tile * AT + alq + 16 * i;
        size_t idx = (((size_t)b * NA + a) * NU + u) * NO;
        vp[i][0] = *(const float4*)(fin + idx);
        vp[i][1] = *(const float4*)(fin + idx + 4);
        vq[i][0] = *(const float4*)(fin2 + idx);
        vq[i][1] = *(const float4*)(fin2 + idx + 4);
    }

    ((float4*)sW)[tid] = ((const float4*)W)[tid];
    if (tid < 128) {
        size_t base = ((size_t)b * NA + (size_t)tile * AT) * NO;
        float4 p = ((const float4*)(g_sgl[si] + base))[tid];
        float4 q = ((const float4*)(g_sgl[si2] + base))[tid];
        p.x = 0.5f * (p.x + q.x); p.y = 0.5f * (p.y + q.y);
        p.z = 0.5f * (p.z + q.z); p.w = 0.5f * (p.w + q.w);
        ((float4*)sSgl)[tid] = p;

        float s = 0.0f, s2 = 0.0f;
        #pragma unroll
        for (int t = 0; t < NT; t++) {
            s  += g_plg[pi][(b * NT + t) * 128 + tid];
            s2 += g_plg[pi2][(b * NT + t) * 128 + tid];
        }
        sFlg[tid] = 0.5f * (s + s2) * (1.0f / NA);
    }
    if (tid < 8) {
        float s = 0.0f, s2 = 0.0f;
        #pragma unroll
        for (int t = 0; t < NT; t++) {
            s  += g_pgg[pi][(b * NT + t) * 8 + tid];
            s2 += g_pgg[pi2][(b * NT + t) * 8 + tid];
        }
        sFgg[tid] = 0.5f * (s + s2) * (1.0f / (NA * NU));
    }
    __syncthreads();

    #pragma unroll
    for (int k = 0; k < 2; k++) {
        int e = tid + 256 * k, br = e >> 7, uu = (e >> 3) & 15, o = e & 7;
        float acc = bias[br * 8 + o];
        #pragma unroll
        for (int c = 0; c < 8; c++) {
            acc += sFgg[c]          * sW[(br * 32 + 24 + c) * 8 + o];
            acc += sFlg[uu * 8 + c] * sW[(br * 32 +  8 + c) * 8 + o];
        }
        sAddU[e] = acc;
    }
    #pragma unroll
    for (int k = 0; k < 8; k++) {
        int e = tid + 256 * k, br = e >> 9, al = (e >> 3) & 63, o = e & 7;
        float acc = 0.0f;
        #pragma unroll
        for (int c = 0; c < 8; c++)
            acc += sSgl[al * 8 + c] * sW[(br * 32 + 16 + c) * 8 + o];
        sAddA[e] = acc * (1.0f / 16.0f);
    }
    __syncthreads();

    float v[4][8];
    #pragma unroll
    for (int i = 0; i < 4; i++) {
        float4 p0 = vp[i][0], p1 = vp[i][1];
        float4 q0 = vq[i][0], q1 = vq[i][1];
        p0.x = 0.5f * (p0.x + q0.x); p0.y = 0.5f * (p0.y + q0.y);
        p0.z = 0.5f * (p0.z + q0.z); p0.w = 0.5f * (p0.w + q0.w);
        p1.x = 0.5f * (p1.x + q1.x); p1.y = 0.5f * (p1.y + q1.y);
        p1.z = 0.5f * (p1.z + q1.z); p1.w = 0.5f * (p1.w + q1.w);
        v[i][0] = p0.x; v[i][1] = p0.y; v[i][2] = p0.z; v[i][3] = p0.w;
        v[i][4] = p1.x; v[i][5] = p1.y; v[i][6] = p1.z; v[i][7] = p1.w;
    }

    branch_full<8, 32, true>(b, tile, tid, v, sW, sAddU, sAddA,
                             g_fll[so], g_sgl[so], sRedLg, sRedGg);
    __syncthreads();
    write_partials(b, tile, tid, po, sRedLg, sRedGg);
}

// =============================================================================
// Layer 7 fused with the final's pointwise work (R15 verbatim)
// =============================================================================
__global__ void __launch_bounds__(256)
k_last(const float* __restrict__ W, const float* __restrict__ bias,
       const float* __restrict__ W8)
{
    const int s7i = 0, p7i = 1, p7o = 0, sF = 2;
    __shared__ float sW[1024], sAddU[512], sAddA[2048];
    __shared__ float sSgl[512], sSgl2[512], sFlg[128], sFgg[8];
    __shared__ float sRedLg[1024], sRedGg[64];
    __shared__ float sW8[32], sGl[512], sDD[64];
    const int tile = blockIdx.x, b = blockIdx.y, tid = threadIdx.x;
    const int u = tid & 15, alq = tid >> 4, warp = tid >> 5, lane = tid & 31;

    const float* __restrict__ fin  = g_fll[s7i];
    const float* __restrict__ fin2 = g_fll[sF];
    float4 vp[4][2], vq[4][2];
    #pragma unroll
    for (int i = 0; i < 4; i++) {
        int a = tile * AT + alq + 16 * i;
        size_t idx = (((size_t)b * NA + a) * NU + u) * NO;
        vp[i][0] = *(const float4*)(fin + idx);
        vp[i][1] = *(const float4*)(fin + idx + 4);
        vq[i][0] = *(const float4*)(fin2 + idx);
        vq[i][1] = *(const float4*)(fin2 + idx + 4);
    }

    ((float4*)sW)[tid] = ((const float4*)W)[tid];
    if (tid < 32) sW8[tid] = W8[tid];
    if (tid < 128) {
        size_t base = ((size_t)b * NA + (size_t)tile * AT) * NO;
        ((float4*)sSgl)[tid]  = ((const float4*)(g_sgl[s7i] + base))[tid];
        ((float4*)sSgl2)[tid] = ((const float4*)(g_sgl[sF]  + base))[tid];

        float s = 0.0f;
        #pragma unroll
        for (int t = 0; t < NT; t++) s += g_plg[p7i][(b * NT + t) * 128 + tid];
        sFlg[tid] = s * (1.0f / NA);
    }
    if (tid < 8) {
        float s = 0.0f;
        #pragma unroll
        for (int t = 0; t < NT; t++) s += g_pgg[p7i][(b * NT + t) * 8 + tid];
        sFgg[tid] = s * (1.0f / (NA * NU));
    }
    __syncthreads();

    #pragma unroll
    for (int k = 0; k < 2; k++) {
        int e = tid + 256 * k, br = e >> 7, uu = (e >> 3) & 15, o = e & 7;
        float acc = bias[br * 8 + o];
        #pragma unroll
        for (int c = 0; c < 8; c++) {
            acc += sFgg[c]          * sW[(br * 32 + 24 + c) * 8 + o];
            acc += sFlg[uu * 8 + c] * sW[(br * 32 +  8 + c) * 8 + o];
        }
        sAddU[e] = acc;
    }
    #pragma unroll
    for (int k = 0; k < 8; k++) {
        int e = tid + 256 * k, br = e >> 9, al = (e >> 3) & 63, o = e & 7;
        float acc = 0.0f;
        #pragma unroll
        for (int c = 0; c < 8; c++)
            acc += sSgl[al * 8 + c] * sW[(br * 32 + 16 + c) * 8 + o];
        sAddA[e] = acc * (1.0f / 16.0f);
    }
    __syncthreads();

    float v[4][8];
    #pragma unroll
    for (int i = 0; i < 4; i++) {
        float4 p0 = vp[i][0], p1 = vp[i][1];
        v[i][0] = p0.x; v[i][1] = p0.y; v[i][2] = p0.z; v[i][3] = p0.w;
        v[i][4] = p1.x; v[i][5] = p1.y; v[i][6] = p1.z; v[i][7] = p1.w;
    }
    u64 q2[4][4];
    #pragma unroll
    for (int i = 0; i < 4; i++) {
        q2[i][0] = repack(vq[i][0].x, vq[i][0].y);
        q2[i][1] = repack(vq[i][0].z, vq[i][0].w);
        q2[i][2] = repack(vq[i][1].x, vq[i][1].y);
        q2[i][3] = repack(vq[i][1].z, vq[i][1].w);
    }
    const ulonglong2* w8p = (const ulonglong2*)sW8;
    const ulonglong2 w8a = w8p[0], w8b = w8p[1];

    #pragma unroll
    for (int br = 0; br < 4; br++) {
        const ulonglong2* aup = (const ulonglong2*)(sAddU + (br * 16 + u) * 8);
        const ulonglong2 au0 = aup[0], au1 = aup[1];
        u64 z2[4][4];
        #pragma unroll
        for (int i = 0; i < 4; i++) {
            const ulonglong2* ap =
                (const ulonglong2*)(sAddA + (br * 64 + alq + 16 * i) * 8);
            ulonglong2 a0 = ap[0], a1 = ap[1];
            ADD2(z2[i][0], au0.x, a0.x);
            ADD2(z2[i][1], au0.y, a0.y);
            ADD2(z2[i][2], au1.x, a1.x);
            ADD2(z2[i][3], au1.y, a1.y);
        }
        #pragma unroll
        for (int c = 0; c < 8; c++) {
            const ulonglong2* wp = (const ulonglong2*)(sW + (br * 32 + c) * 8);
            const ulonglong2 w0 = wp[0], w1 = wp[1];
            #pragma unroll
            for (int i = 0; i < 4; i++) {
                u64 v2 = pack2(v[i][c]);
                FMA2(z2[i][0], v2, w0.x, z2[i][0]);
                FMA2(z2[i][1], v2, w0.y, z2[i][1]);
                FMA2(z2[i][2], v2, w1.x, z2[i][2]);
                FMA2(z2[i][3], v2, w1.y, z2[i][3]);
            }
        }
        #pragma unroll
        for (int i = 0; i < 4; i++)
            #pragma unroll
            for (int j = 0; j < 4; j++)
                z2[i][j] = relu2(z2[i][j]);

        if (br == 0) {
            #pragma unroll
            for (int i = 0; i < 4; i++) {
                u64 acc2 = 0, t;
                ADD2(t, z2[i][0], q2[i][0]); FMA2(acc2, t, w8a.x, acc2);
                ADD2(t, z2[i][1], q2[i][1]); FMA2(acc2, t, w8a.y, acc2);
                ADD2(t, z2[i][2], q2[i][2]); FMA2(acc2, t, w8b.x, acc2);
                ADD2(t, z2[i][3], q2[i][3]); FMA2(acc2, t, w8b.y, acc2);
                float2 p = unpack2(acc2);
                float dd = 0.5f * (p.x + p.y);
                dd += __shfl_xor_sync(0xffffffffu, dd, 1, 16);
                dd += __shfl_xor_sync(0xffffffffu, dd, 2, 16);
                dd += __shfl_xor_sync(0xffffffffu, dd, 4, 16);
                dd += __shfl_xor_sync(0xffffffffu, dd, 8, 16);
                if (u == 0) sDD[alq + 16 * i] = dd;
            }
        } else if (br == 1) {
            u64 acc[4];
            #pragma unroll
            for (int j = 0; j < 4; j++) {
                u64 t0, t1;
                ADD2(t0, z2[0][j], z2[1][j]);
                ADD2(t1, z2[2][j], z2[3][j]);
                ADD2(acc[j], t0, t1);
            }
            const bool hA = (lane & 16);
            u64 sa = hA ? acc[0] : acc[2];
            u64 sb = hA ? acc[1] : acc[3];
            u64 ka = hA ? acc[2] : acc[0];
            u64 kb = hA ? acc[3] : acc[1];
            u64 ra = shfl64(sa, 16), rb = shfl64(sb, 16);
            ADD2(ka, ka, ra); ADD2(kb, kb, rb);
            ulonglong2 st; st.x = ka; st.y = kb;
            *(ulonglong2*)(sRedLg + warp * 128 + u * 8 + (hA ? 4 : 0)) = st;
        } else if (br == 2) {
            const bool h8 = (u & 8), h4 = (u & 4), h2 = (u & 2);
            #pragma unroll
            for (int i = 0; i < 4; i++) {
                u64 sa = h8 ? z2[i][0] : z2[i][2];
                u64 sb = h8 ? z2[i][1] : z2[i][3];
                u64 ka = h8 ? z2[i][2] : z2[i][0];
                u64 kb = h8 ? z2[i][3] : z2[i][1];
                u64 ra = shfl64(sa, 8), rb = shfl64(sb, 8);
                ADD2(ka, ka, ra); ADD2(kb, kb, rb);
                u64 s1 = h4 ? ka : kb, k1 = h4 ? kb : ka;
                u64 r1 = shfl64(s1, 4);
                ADD2(k1, k1, r1);
                float2 p = unpack2(k1);
                float snd = h2 ? p.x : p.y;
                float t = (h2 ? p.y : p.x) + __shfl_xor_sync(0xffffffffu, snd, 2);
                t += __shfl_xor_sync(0xffffffffu, t, 1);
                if (!(u & 1)) {
                    int o = (h8 ? 4 : 0) + (h4 ? 2 : 0) + (h2 ? 1 : 0);
                    sGl[(alq + 16 * i) * 8 + o] = t;
                }
            }
        } else {
            u64 acc[4];
            #pragma unroll
            for (int j = 0; j < 4; j++) {
                u64 t0, t1;
                ADD2(t0, z2[0][j], z2[1][j]);
                ADD2(t1, z2[2][j], z2[3][j]);
                ADD2(acc[j], t0, t1);
            }
            const bool b0 = (lane & 1), b1 = (lane & 2), b2 = (lane & 4);
            u64 sa = b0 ? acc[0] : acc[2];
            u64 sb = b0 ? acc[1] : acc[3];
            u64 ka = b0 ? acc[2] : acc[0];
            u64 kb = b0 ? acc[3] : acc[1];
            u64 ra = shfl64(sa, 1), rb = shfl64(sb, 1);
            ADD2(ka, ka, ra); ADD2(kb, kb, rb);
            u64 s1 = b1 ? ka : kb, k1 = b1 ? kb : ka;
            u64 r1 = shfl64(s1, 2);
            ADD2(k1, k1, r1);
            float2 p = unpack2(k1);
            float snd = b2 ? p.x : p.y;
            float t = (b2 ? p.y : p.x) + __shfl_xor_sync(0xffffffffu, snd, 4);
            t += __shfl_xor_sync(0xffffffffu, t, 8);
            t += __shfl_xor_sync(0xffffffffu, t, 16);
            if (lane < 8) {
                int o = (b0 ? 4 : 0) + (b1 ? 2 : 0) + (b2 ? 1 : 0);
                sRedGg[warp * 8 + o] = t;
            }
        }
    }
    __syncthreads();
    write_partials(b, tile, tid, p7o, sRedLg, sRedGg);
    if (tid < 64) {
        int al = tid, a = tile * AT + al;
        float g = 0.0f;
        #pragma unroll
        for (int c = 0; c < 8; c++)
            g += 0.5f * (sGl[al * 8 + c] + sSgl2[al * 8 + c]) * sW8[16 + c];
        g_outp[b * NA + a] = (sDD[al] + g) * (1.0f / 16.0f);
    }
}

// =============================================================================
// Tiny final (R15 verbatim)
// =============================================================================
__global__ void __launch_bounds__(256)
k_fin2(const float* __restrict__ W8, const float* __restrict__ b8,
       float* __restrict__ out, int p1, int p2)
{
    __shared__ float sW8[32];
    __shared__ float sFlg[128], sFgg[8];
    __shared__ float cU[17];
    const int b = blockIdx.x, tid = threadIdx.x;
    if (tid < 32) sW8[tid] = W8[tid];
    if (tid < 128) {
        float s = 0.0f;
        #pragma unroll
        for (int t = 0; t < NT; t++)
            s += g_plg[p1][(b * NT + t) * 128 + tid] +
                 g_plg[p2][(b * NT + t) * 128 + tid];
        sFlg[tid] = s * (0.5f / NA);
    }
    if (tid < 8) {
        float s = 0.0f;
        #pragma unroll
        for (int t = 0; t < NT; t++)
            s += g_pgg[p1][(b * NT + t) * 8 + tid] +
                 g_pgg[p2][(b * NT + t) * 8 + tid];
        sFgg[tid] = s * (0.5f / (NA * NU));
    }
    __syncthreads();
    if (tid < 16) {
        float s = 0.0f;
        #pragma unroll
        for (int c = 0; c < 8; c++)
            s += sFlg[tid * 8 + c] * sW8[8 + c];
        cU[tid] = s;
    }
    __syncthreads();
    if (tid == 0) {
        float s = 0.0f;
        for (int uu = 0; uu < 16; uu++) s += cU[uu];
        s *= (1.0f / 16.0f);
        #pragma unroll
        for (int c = 0; c < 8; c++) s += sFgg[c] * sW8[24 + c];
        s += b8[0];
        cU[16] = s;
    }
    __syncthreads();
    const float cb = cU[16];
    #pragma unroll
    for (int k = 0; k < 4; k++) {
        int a = tid + 256 * k;
        out[(size_t)b * NA + a] =
            3.14159265358979323846f * (g_outp[b * NA + a] + cb);
    }
}

// =============================================================================
extern "C" void kernel_launch(void* const* d_in, const int* in_sizes, int n_in,
                              void* d_out, int out_size)
{
    const float* channel = (const float*)d_in[0];
    const float* W1 = (const float*)d_in[1];
    const float* b1 = (const float*)d_in[2];
    const float* Wm = (const float*)d_in[3];
    const float* bm = (const float*)d_in[4];
    const float* W8 = (const float*)d_in[5];
    const float* b8 = (const float*)d_in[6];
    float* out = (float*)d_out;

    dim3 grd(NT, NB);
    k_layer1<<<grd, 256>>>(channel, W1, b1);
    k_main_ns<<<grd, 256>>>(Wm + 0 * 1024, bm + 0 * 32, 0, 1, 0, 1);
    k_main_ns<<<grd, 256>>>(Wm + 1 * 1024, bm + 1 * 32, 1, 2, 1, 2);
    k_main_ns<<<grd, 256>>>(Wm + 2 * 1024, bm + 2 * 32, 2, 1, 2, 1);
    k_main_ns<<<grd, 256>>>(Wm + 3 * 1024, bm + 3 * 32, 1, 1, 1, 3);
    k_main_skip<<<grd, 256>>>(Wm + 4 * 1024, bm + 4 * 32, 1, 0, 0, 3, 0, 1);
    k_last<<<grd, 256>>>(Wm + 5 * 1024, bm + 5 * 32, W8);
    k_fin2<<<NB, 256>>>(W8, b8, out, 0, 2);
}